// round 2
// baseline (speedup 1.0000x reference)
#include <cuda_runtime.h>
#include <cstdint>
#include <cstddef>

// ---------------------------------------------------------------------------
// Problem constants
// ---------------------------------------------------------------------------
#define C_DIM 512
#define HW    4096
#define BATCH 4
#define KCOL  (C_DIM * 9)   // 4608 = im2col K for 3x3 conv

// ---------------------------------------------------------------------------
// Device-global scratch (no cudaMalloc allowed).
// Lifetime-aliased arena:
//   g_big : im2col col buffer (steps 2-5, 302 MB)  THEN  attn logits S (steps 6-8, 268 MB)
//   g_h   : LN output h (steps 1-3)                THEN  attn output O (steps 8-9)
// ---------------------------------------------------------------------------
#define COL_BYTES ((size_t)BATCH * KCOL * HW * sizeof(float))   // 302 MB
__device__ __align__(256) unsigned char g_big[COL_BYTES];
__device__ float g_h[(size_t)BATCH * C_DIM * HW];   // 32 MB (h, later o)
__device__ float g_q[(size_t)BATCH * C_DIM * HW];
__device__ float g_k[(size_t)BATCH * C_DIM * HW];
__device__ float g_v[(size_t)BATCH * C_DIM * HW];

// ---------------------------------------------------------------------------
// Helpers
// ---------------------------------------------------------------------------
__device__ __forceinline__ float tf32r(float x) {
    unsigned u;
    asm("cvt.rna.tf32.f32 %0, %1;" : "=r"(u) : "f"(x));
    return __uint_as_float(u);
}

// ---------------------------------------------------------------------------
// LayerNorm over channels (per b,h,w position)
// ---------------------------------------------------------------------------
__global__ void ln_kernel(const float* __restrict__ x,
                          const float* __restrict__ w,
                          const float* __restrict__ b,
                          float* __restrict__ h) {
    int idx = blockIdx.x * blockDim.x + threadIdx.x;   // 0 .. BATCH*HW-1
    int bb = idx >> 12;
    int p  = idx & (HW - 1);
    const float* xp = x + (size_t)bb * C_DIM * HW + p;
    float s = 0.f, ss = 0.f;
#pragma unroll 8
    for (int c = 0; c < C_DIM; c++) {
        float v = xp[(size_t)c * HW];
        s += v; ss += v * v;
    }
    float mean = s * (1.f / C_DIM);
    float var  = ss * (1.f / C_DIM) - mean * mean;
    float rstd = rsqrtf(var + 1e-6f);
    float* hp = h + (size_t)bb * C_DIM * HW + p;
#pragma unroll 8
    for (int c = 0; c < C_DIM; c++) {
        hp[(size_t)c * HW] = w[c] * ((xp[(size_t)c * HW] - mean) * rstd) + b[c];
    }
}

// ---------------------------------------------------------------------------
// im2col for 3x3 pad-1 conv: col[b][ci*9+tap][p]   (matches OIHW weight layout)
// ---------------------------------------------------------------------------
__global__ void im2col_kernel(const float* __restrict__ h, float* __restrict__ col) {
    int p  = blockIdx.x * blockDim.x + threadIdx.x;   // 0..4095
    int r  = blockIdx.y;                              // bb*KCOL + kk
    int bb = r / KCOL;
    int kk = r - bb * KCOL;
    int ci  = kk / 9;
    int tap = kk - ci * 9;
    int dy = tap / 3 - 1;
    int dx = tap - (tap / 3) * 3 - 1;
    int y = p >> 6, x0 = p & 63;
    int yy = y + dy, xx = x0 + dx;
    float v = 0.f;
    if ((unsigned)yy < 64u && (unsigned)xx < 64u)
        v = h[(size_t)bb * C_DIM * HW + (size_t)ci * HW + yy * 64 + xx];
    col[(size_t)r * HW + p] = v;
}

// ---------------------------------------------------------------------------
// Generic TF32 tensor-core GEMM: C[M,N] = op(A)[M,K] * op(B)[K,N]
//   TA=false: A[m*lda+k]   TA=true: A[k*lda+m]
//   TB=false: B[k*ldb+n]   TB=true: B[n*ldb+k]
//   EPI 0: C=acc   1: C=acc*alpha   2: C=acc+bias[m]+resid[m,n]
// blockIdx.z = batch. All dims are multiples of tile sizes (no bounds checks).
// ---------------------------------------------------------------------------
#define BM 128
#define BN 128
#define BK 16

template<bool TA, bool TB, int EPI>
__global__ __launch_bounds__(256)
void gemm_tf32(const float* __restrict__ Ab, const float* __restrict__ Bb,
               float* __restrict__ Cb,
               int M, int N, int K,
               int lda, int ldb, int ldc,
               size_t sA, size_t sB, size_t sC,
               float alpha,
               const float* __restrict__ bias,
               const float* __restrict__ resid, size_t sR) {
    __shared__ __align__(16) float As[2][BK][BM + 4];
    __shared__ __align__(16) float Bs[2][BK][BN + 4];

    const int tid  = threadIdx.x;
    const int lane = tid & 31;
    const int warp = tid >> 5;
    const int wm = warp & 1;    // warp grid 2 (m) x 4 (n)
    const int wn = warp >> 1;
    const int bz = blockIdx.z;
    const int m0 = blockIdx.y * BM;
    const int n0 = blockIdx.x * BN;

    const float* A = Ab + sA * bz;
    const float* B = Bb + sB * bz;

    float acc[4][4][4];
#pragma unroll
    for (int i = 0; i < 4; i++)
#pragma unroll
        for (int j = 0; j < 4; j++)
#pragma unroll
            for (int r = 0; r < 4; r++) acc[i][j][r] = 0.f;

    float4 ra[2], rb[2];

    auto ldA = [&](int k0) {
#pragma unroll
        for (int i = 0; i < 2; i++) {
            int v = tid + i * 256;
            if (TA) { int kr = v >> 5, mv = (v & 31) << 2;
                ra[i] = *(const float4*)(A + (size_t)(k0 + kr) * lda + (m0 + mv)); }
            else    { int mr = v >> 2, kv = (v & 3) << 2;
                ra[i] = *(const float4*)(A + (size_t)(m0 + mr) * lda + (k0 + kv)); }
        }
    };
    auto ldB = [&](int k0) {
#pragma unroll
        for (int i = 0; i < 2; i++) {
            int v = tid + i * 256;
            if (!TB) { int kr = v >> 5, nv = (v & 31) << 2;
                rb[i] = *(const float4*)(B + (size_t)(k0 + kr) * ldb + (n0 + nv)); }
            else     { int nr = v >> 2, kv = (v & 3) << 2;
                rb[i] = *(const float4*)(B + (size_t)(n0 + nr) * ldb + (k0 + kv)); }
        }
    };
    auto stA = [&](int buf) {
#pragma unroll
        for (int i = 0; i < 2; i++) {
            int v = tid + i * 256;
            if (TA) { int kr = v >> 5, mv = (v & 31) << 2;
                float4 t = ra[i];
                float4 c = make_float4(tf32r(t.x), tf32r(t.y), tf32r(t.z), tf32r(t.w));
                *(float4*)&As[buf][kr][mv] = c; }
            else    { int mr = v >> 2, kv = (v & 3) << 2;
                float4 t = ra[i];
                As[buf][kv + 0][mr] = tf32r(t.x);
                As[buf][kv + 1][mr] = tf32r(t.y);
                As[buf][kv + 2][mr] = tf32r(t.z);
                As[buf][kv + 3][mr] = tf32r(t.w); }
        }
    };
    auto stB = [&](int buf) {
#pragma unroll
        for (int i = 0; i < 2; i++) {
            int v = tid + i * 256;
            if (!TB) { int kr = v >> 5, nv = (v & 31) << 2;
                float4 t = rb[i];
                float4 c = make_float4(tf32r(t.x), tf32r(t.y), tf32r(t.z), tf32r(t.w));
                *(float4*)&Bs[buf][kr][nv] = c; }
            else     { int nr = v >> 2, kv = (v & 3) << 2;
                float4 t = rb[i];
                Bs[buf][kv + 0][nr] = tf32r(t.x);
                Bs[buf][kv + 1][nr] = tf32r(t.y);
                Bs[buf][kv + 2][nr] = tf32r(t.z);
                Bs[buf][kv + 3][nr] = tf32r(t.w); }
        }
    };

    auto compute = [&](int buf) {
#pragma unroll
        for (int ks = 0; ks < 2; ks++) {
            const int kb = ks * 8;
            unsigned af[4][4], bf[4][2];
#pragma unroll
            for (int mi = 0; mi < 4; mi++) {
                int r0 = wm * 64 + mi * 16 + (lane >> 2);
                int c0 = kb + (lane & 3);
                af[mi][0] = __float_as_uint(As[buf][c0    ][r0    ]);
                af[mi][1] = __float_as_uint(As[buf][c0    ][r0 + 8]);
                af[mi][2] = __float_as_uint(As[buf][c0 + 4][r0    ]);
                af[mi][3] = __float_as_uint(As[buf][c0 + 4][r0 + 8]);
            }
#pragma unroll
            for (int ni = 0; ni < 4; ni++) {
                int cc = wn * 32 + ni * 8 + (lane >> 2);
                int rr = kb + (lane & 3);
                bf[ni][0] = __float_as_uint(Bs[buf][rr    ][cc]);
                bf[ni][1] = __float_as_uint(Bs[buf][rr + 4][cc]);
            }
#pragma unroll
            for (int mi = 0; mi < 4; mi++)
#pragma unroll
                for (int ni = 0; ni < 4; ni++) {
                    asm volatile(
                        "mma.sync.aligned.m16n8k8.row.col.f32.tf32.tf32.f32 "
                        "{%0,%1,%2,%3}, {%4,%5,%6,%7}, {%8,%9}, {%0,%1,%2,%3};\n"
                        : "+f"(acc[mi][ni][0]), "+f"(acc[mi][ni][1]),
                          "+f"(acc[mi][ni][2]), "+f"(acc[mi][ni][3])
                        : "r"(af[mi][0]), "r"(af[mi][1]), "r"(af[mi][2]), "r"(af[mi][3]),
                          "r"(bf[ni][0]), "r"(bf[ni][1]));
                }
        }
    };

    // Main loop: single barrier per iteration.
    //   ld(t+1) -> compute(t) -> st(t+1 into other buffer) -> sync
    // stA/stB write buffer (t+1)&1 which compute(t) does not touch; its previous
    // readers (iteration t-1) were fenced by the barrier at the end of t-1.
    const int NT = K / BK;
    ldA(0); ldB(0);
    stA(0); stB(0);
    __syncthreads();
    for (int t = 0; t < NT; t++) {
        if (t + 1 < NT) { ldA((t + 1) * BK); ldB((t + 1) * BK); }  // ldg overlaps compute
        compute(t & 1);
        if (t + 1 < NT) { stA((t + 1) & 1); stB((t + 1) & 1); }
        __syncthreads();
    }

    // Epilogue
    float* Cp = Cb + sC * bz;
    const float* Rp = (EPI == 2) ? (resid + sR * bz) : nullptr;
#pragma unroll
    for (int mi = 0; mi < 4; mi++) {
        int r0 = m0 + wm * 64 + mi * 16 + (lane >> 2);
#pragma unroll
        for (int ni = 0; ni < 4; ni++) {
            int c0 = n0 + wn * 32 + ni * 8 + ((lane & 3) << 1);
            float v0 = acc[mi][ni][0], v1 = acc[mi][ni][1];
            float v2 = acc[mi][ni][2], v3 = acc[mi][ni][3];
            if (EPI == 1) { v0 *= alpha; v1 *= alpha; v2 *= alpha; v3 *= alpha; }
            if (EPI == 2) {
                float b0 = bias[r0], b1 = bias[r0 + 8];
                v0 += b0 + Rp[(size_t)r0 * ldc + c0];
                v1 += b0 + Rp[(size_t)r0 * ldc + c0 + 1];
                v2 += b1 + Rp[(size_t)(r0 + 8) * ldc + c0];
                v3 += b1 + Rp[(size_t)(r0 + 8) * ldc + c0 + 1];
            }
            *(float2*)(Cp + (size_t)r0       * ldc + c0) = make_float2(v0, v1);
            *(float2*)(Cp + (size_t)(r0 + 8) * ldc + c0) = make_float2(v2, v3);
        }
    }
}

// ---------------------------------------------------------------------------
// Row softmax over 4096 keys, in place. One block per (b, query) row.
// ---------------------------------------------------------------------------
__global__ __launch_bounds__(256) void softmax_kernel(float* __restrict__ S) {
    size_t row = blockIdx.x;
    float* r = S + row * (size_t)HW;
    int tid = threadIdx.x;
    float4 v[4];
    float mx = -3.4e38f;
#pragma unroll
    for (int i = 0; i < 4; i++) {
        v[i] = ((const float4*)r)[tid + i * 256];
        mx = fmaxf(mx, fmaxf(fmaxf(v[i].x, v[i].y), fmaxf(v[i].z, v[i].w)));
    }
#pragma unroll
    for (int o = 16; o > 0; o >>= 1) mx = fmaxf(mx, __shfl_xor_sync(0xffffffffu, mx, o));
    __shared__ float sred[8];
    if ((tid & 31) == 0) sred[tid >> 5] = mx;
    __syncthreads();
    float bm = sred[0];
#pragma unroll
    for (int i = 1; i < 8; i++) bm = fmaxf(bm, sred[i]);
    __syncthreads();
    const float L2E = 1.4426950408889634f;
    float sum = 0.f;
#pragma unroll
    for (int i = 0; i < 4; i++) {
        v[i].x = exp2f((v[i].x - bm) * L2E);
        v[i].y = exp2f((v[i].y - bm) * L2E);
        v[i].z = exp2f((v[i].z - bm) * L2E);
        v[i].w = exp2f((v[i].w - bm) * L2E);
        sum += v[i].x + v[i].y + v[i].z + v[i].w;
    }
#pragma unroll
    for (int o = 16; o > 0; o >>= 1) sum += __shfl_xor_sync(0xffffffffu, sum, o);
    if ((tid & 31) == 0) sred[tid >> 5] = sum;
    __syncthreads();
    float ts = 0.f;
#pragma unroll
    for (int i = 0; i < 8; i++) ts += sred[i];
    float inv = 1.f / ts;
#pragma unroll
    for (int i = 0; i < 4; i++) {
        v[i].x *= inv; v[i].y *= inv; v[i].z *= inv; v[i].w *= inv;
        ((float4*)r)[tid + i * 256] = v[i];
    }
}

// ---------------------------------------------------------------------------
// Launch
// ---------------------------------------------------------------------------
extern "C" void kernel_launch(void* const* d_in, const int* in_sizes, int n_in,
                              void* d_out, int out_size) {
    const float* x    = (const float*)d_in[0];
    const float* ln_w = (const float*)d_in[1];
    const float* ln_b = (const float*)d_in[2];
    const float* wq   = (const float*)d_in[3];
    const float* wk   = (const float*)d_in[4];
    const float* wv   = (const float*)d_in[5];
    const float* wp   = (const float*)d_in[6];
    const float* bp   = (const float*)d_in[7];
    float* out = (float*)d_out;

    void *big_p, *h_p, *q_p, *k_p, *v_p;
    cudaGetSymbolAddress(&big_p, g_big);
    cudaGetSymbolAddress(&h_p,   g_h);
    cudaGetSymbolAddress(&q_p,   g_q);
    cudaGetSymbolAddress(&k_p,   g_k);
    cudaGetSymbolAddress(&v_p,   g_v);
    float* col = (float*)big_p;    // steps 2-5
    float* s   = (float*)big_p;    // steps 6-8 (aliases col; disjoint lifetime)
    float* h   = (float*)h_p;      // steps 1-3
    float* o   = (float*)h_p;      // steps 8-9 (aliases h; disjoint lifetime)
    float* q   = (float*)q_p;
    float* k   = (float*)k_p;
    float* v   = (float*)v_p;

    const size_t sCHW = (size_t)C_DIM * HW;      // per-batch activation stride
    const size_t sCOL = (size_t)KCOL * HW;       // per-batch col stride
    const size_t sS   = (size_t)HW * HW;         // per-batch attn stride
    const float attn_scale = 0.04419417382415922f;  // 512^-0.5

    // 1. LayerNorm
    ln_kernel<<<(BATCH * HW) / 256, 256>>>(x, ln_w, ln_b, h);

    // 2. im2col (shared by K and V convs)
    im2col_kernel<<<dim3(HW / 256, BATCH * KCOL), 256>>>(h, col);

    // 3. Q = Wq * h           [512 x 4096, K=512]
    gemm_tf32<false, false, 0><<<dim3(HW / BN, C_DIM / BM, BATCH), 256>>>(
        wq, h, q, C_DIM, HW, C_DIM, C_DIM, HW, HW,
        0, sCHW, sCHW, 1.f, nullptr, nullptr, 0);

    // 4. K = Wk * col         [512 x 4096, K=4608]
    gemm_tf32<false, false, 0><<<dim3(HW / BN, C_DIM / BM, BATCH), 256>>>(
        wk, col, k, C_DIM, HW, KCOL, KCOL, HW, HW,
        0, sCOL, sCHW, 1.f, nullptr, nullptr, 0);

    // 5. V = Wv * col
    gemm_tf32<false, false, 0><<<dim3(HW / BN, C_DIM / BM, BATCH), 256>>>(
        wv, col, v, C_DIM, HW, KCOL, KCOL, HW, HW,
        0, sCOL, sCHW, 1.f, nullptr, nullptr, 0);

    // 6. S = (Q^T K) * scale  [4096 x 4096, K=512]  (A transposed layout)
    gemm_tf32<true, false, 1><<<dim3(HW / BN, HW / BM, BATCH), 256>>>(
        q, k, s, HW, HW, C_DIM, HW, HW, HW,
        sCHW, sCHW, sS, attn_scale, nullptr, nullptr, 0);

    // 7. row softmax over keys, in place
    softmax_kernel<<<BATCH * HW, 256>>>(s);

    // 8. O = V * P^T          [512 x 4096, K=4096]  (B transposed layout)
    gemm_tf32<false, true, 0><<<dim3(HW / BN, C_DIM / BM, BATCH), 256>>>(
        v, s, o, C_DIM, HW, HW, HW, HW, HW,
        sCHW, sS, sCHW, 1.f, nullptr, nullptr, 0);

    // 9. out = x + Wp * O + bp  (fused bias + residual epilogue)
    gemm_tf32<false, false, 2><<<dim3(HW / BN, C_DIM / BM, BATCH), 256>>>(
        wp, o, out, C_DIM, HW, C_DIM, C_DIM, HW, HW,
        0, sCHW, sCHW, 1.f, bp, x, sCHW);
}

// round 3
// speedup vs baseline: 1.9477x; 1.9477x over previous
#include <cuda_runtime.h>
#include <cuda_fp16.h>
#include <cstdint>
#include <cstddef>

// ---------------------------------------------------------------------------
// Problem constants
// ---------------------------------------------------------------------------
#define C_DIM 512
#define HW    4096
#define BATCH 4
#define KCOL  (C_DIM * 9)   // 4608 = im2col K for 3x3 conv

// ---------------------------------------------------------------------------
// Device-global scratch (no cudaMalloc allowed).
//   g_big : im2col col buffer (steps 2-5)  THEN  attn logits S (steps 6-8)
//   g_h   : LN output h (steps 1-3)        THEN  attn output O (steps 8-9)
// ---------------------------------------------------------------------------
#define COL_BYTES ((size_t)BATCH * KCOL * HW * sizeof(float))   // 302 MB
__device__ __align__(256) unsigned char g_big[COL_BYTES];
__device__ float g_h[(size_t)BATCH * C_DIM * HW];
__device__ float g_q[(size_t)BATCH * C_DIM * HW];
__device__ float g_k[(size_t)BATCH * C_DIM * HW];
__device__ float g_v[(size_t)BATCH * C_DIM * HW];

// ---------------------------------------------------------------------------
// Helpers
// ---------------------------------------------------------------------------
__device__ __forceinline__ uint32_t s2u(const void* p) {
    return (uint32_t)__cvta_generic_to_shared(p);
}
__device__ __forceinline__ uint2 f4_to_h4(float4 t) {
    __half2 h0 = __floats2half2_rn(t.x, t.y);
    __half2 h1 = __floats2half2_rn(t.z, t.w);
    uint2 r;
    r.x = *reinterpret_cast<uint32_t*>(&h0);
    r.y = *reinterpret_cast<uint32_t*>(&h1);
    return r;
}

#define LDSM_X4(r0, r1, r2, r3, addr)                                         \
    asm volatile("ldmatrix.sync.aligned.m8n8.x4.shared.b16 {%0,%1,%2,%3}, [%4];" \
                 : "=r"(r0), "=r"(r1), "=r"(r2), "=r"(r3) : "r"(addr))
#define LDSM_X4_T(r0, r1, r2, r3, addr)                                       \
    asm volatile("ldmatrix.sync.aligned.m8n8.x4.trans.shared.b16 {%0,%1,%2,%3}, [%4];" \
                 : "=r"(r0), "=r"(r1), "=r"(r2), "=r"(r3) : "r"(addr))

// ---------------------------------------------------------------------------
// LayerNorm over channels (per b,h,w position)
// ---------------------------------------------------------------------------
__global__ void ln_kernel(const float* __restrict__ x,
                          const float* __restrict__ w,
                          const float* __restrict__ b,
                          float* __restrict__ h) {
    int idx = blockIdx.x * blockDim.x + threadIdx.x;   // 0 .. BATCH*HW-1
    int bb = idx >> 12;
    int p  = idx & (HW - 1);
    const float* xp = x + (size_t)bb * C_DIM * HW + p;
    float s = 0.f, ss = 0.f;
#pragma unroll 8
    for (int c = 0; c < C_DIM; c++) {
        float v = xp[(size_t)c * HW];
        s += v; ss += v * v;
    }
    float mean = s * (1.f / C_DIM);
    float var  = ss * (1.f / C_DIM) - mean * mean;
    float rstd = rsqrtf(var + 1e-6f);
    float* hp = h + (size_t)bb * C_DIM * HW + p;
#pragma unroll 8
    for (int c = 0; c < C_DIM; c++) {
        hp[(size_t)c * HW] = w[c] * ((xp[(size_t)c * HW] - mean) * rstd) + b[c];
    }
}

// ---------------------------------------------------------------------------
// im2col for 3x3 pad-1 conv: col[b][ci*9+tap][p]   (matches OIHW weight layout)
// ---------------------------------------------------------------------------
__global__ void im2col_kernel(const float* __restrict__ h, float* __restrict__ col) {
    int p  = blockIdx.x * blockDim.x + threadIdx.x;   // 0..4095
    int r  = blockIdx.y;                              // bb*KCOL + kk
    int bb = r / KCOL;
    int kk = r - bb * KCOL;
    int ci  = kk / 9;
    int tap = kk - ci * 9;
    int dy = tap / 3 - 1;
    int dx = tap - (tap / 3) * 3 - 1;
    int y = p >> 6, x0 = p & 63;
    int yy = y + dy, xx = x0 + dx;
    float v = 0.f;
    if ((unsigned)yy < 64u && (unsigned)xx < 64u)
        v = h[(size_t)bb * C_DIM * HW + (size_t)ci * HW + yy * 64 + xx];
    col[(size_t)r * HW + p] = v;
}

// ---------------------------------------------------------------------------
// fp16 tensor-core GEMM (fp32 in/out, fp32 accumulate):
//   C[M,N] = op(A)[M,K] * op(B)[K,N]
//   TA=false: A[m*lda+k]   TA=true: A[k*lda+m]
//   TB=false: B[k*ldb+n]   TB=true: B[n*ldb+k]
//   EPI 0: C=acc   1: C=acc*alpha   2: C=acc+bias[m]+resid[m,n]
// Tile: 128x128x32, 8 warps (2x4), warp tile 64x32, mma.m16n8k16.
// Smem keeps the GLOBAL contiguous dim contiguous; ldmatrix(.trans) does the
// transpose at fragment-load time. All dims multiples of tile sizes.
// ---------------------------------------------------------------------------
#define BM 128
#define BN 128
#define BKH 32

template<bool TA, bool TB, int EPI>
__global__ __launch_bounds__(256)
void gemm_f16(const float* __restrict__ Ab, const float* __restrict__ Bb,
              float* __restrict__ Cb,
              int M, int N, int K,
              int lda, int ldb, int ldc,
              size_t sA, size_t sB, size_t sC,
              float alpha,
              const float* __restrict__ bias,
              const float* __restrict__ resid, size_t sR) {
    // A smem: !TA -> [m][k] (k contig, stride 40h=80B);  TA -> [k][m] (m contig, stride 136h=272B)
    constexpr int AR = TA ? BKH : BM;
    constexpr int AC = (TA ? BM : BKH) + 8;
    // B smem: !TB -> [k][n] (n contig, 272B stride);     TB -> [n][k] (k contig, 80B stride)
    constexpr int BR = TB ? BN : BKH;
    constexpr int BC = (TB ? BKH : BN) + 8;
    __shared__ __align__(16) __half As[2][AR][AC];
    __shared__ __align__(16) __half Bs[2][BR][BC];

    const int tid  = threadIdx.x;
    const int lane = tid & 31;
    const int warp = tid >> 5;
    const int wm = warp & 1;    // warp grid 2 (m) x 4 (n)
    const int wn = warp >> 1;
    const int bz = blockIdx.z;
    const int m0 = blockIdx.y * BM;
    const int n0 = blockIdx.x * BN;

    const float* A = Ab + sA * bz;
    const float* B = Bb + sB * bz;

    float acc[4][4][4];
#pragma unroll
    for (int i = 0; i < 4; i++)
#pragma unroll
        for (int j = 0; j < 4; j++)
#pragma unroll
            for (int r = 0; r < 4; r++) acc[i][j][r] = 0.f;

    uint2 ra[4], rb[4];   // staged half4 per thread (4 x 1024 elems per tile)

    auto ldA = [&](int k0) {
#pragma unroll
        for (int i = 0; i < 4; i++) {
            int idx = tid + i * 256;
            float4 t;
            if (TA) { int kr = idx >> 5, mv = (idx & 31) << 2;         // 32 rows x 32 float4
                t = *(const float4*)(A + (size_t)(k0 + kr) * lda + (m0 + mv)); }
            else    { int mr = idx >> 3, kv = (idx & 7) << 2;          // 128 rows x 8 float4
                t = *(const float4*)(A + (size_t)(m0 + mr) * lda + (k0 + kv)); }
            ra[i] = f4_to_h4(t);
        }
    };
    auto ldB = [&](int k0) {
#pragma unroll
        for (int i = 0; i < 4; i++) {
            int idx = tid + i * 256;
            float4 t;
            if (!TB) { int kr = idx >> 5, nv = (idx & 31) << 2;
                t = *(const float4*)(B + (size_t)(k0 + kr) * ldb + (n0 + nv)); }
            else     { int nr = idx >> 3, kv = (idx & 7) << 2;
                t = *(const float4*)(B + (size_t)(n0 + nr) * ldb + (k0 + kv)); }
            rb[i] = f4_to_h4(t);
        }
    };
    auto stA = [&](int buf) {
#pragma unroll
        for (int i = 0; i < 4; i++) {
            int idx = tid + i * 256;
            if (TA) { int kr = idx >> 5, mv = (idx & 31) << 2;
                *(uint2*)&As[buf][kr][mv] = ra[i]; }
            else    { int mr = idx >> 3, kv = (idx & 7) << 2;
                *(uint2*)&As[buf][mr][kv] = ra[i]; }
        }
    };
    auto stB = [&](int buf) {
#pragma unroll
        for (int i = 0; i < 4; i++) {
            int idx = tid + i * 256;
            if (!TB) { int kr = idx >> 5, nv = (idx & 31) << 2;
                *(uint2*)&Bs[buf][kr][nv] = rb[i]; }
            else     { int nr = idx >> 3, kv = (idx & 7) << 2;
                *(uint2*)&Bs[buf][nr][kv] = rb[i]; }
        }
    };

    auto compute = [&](int buf) {
#pragma unroll
        for (int ks = 0; ks < 2; ks++) {
            const int k0 = ks * 16;
            uint32_t af[4][4], bf[4][2];
            // A fragments: one ldmatrix.x4 per 16-row tile
#pragma unroll
            for (int mi = 0; mi < 4; mi++) {
                int m0w = wm * 64 + mi * 16;
                if (!TA) {
                    uint32_t addr = s2u(&As[buf][m0w + (lane & 15)][k0 + ((lane >> 4) << 3)]);
                    LDSM_X4(af[mi][0], af[mi][1], af[mi][2], af[mi][3], addr);
                } else {
                    uint32_t addr = s2u(&As[buf][k0 + (lane & 7) + ((lane >> 4) << 3)]
                                            [m0w + (((lane >> 3) & 1) << 3)]);
                    LDSM_X4_T(af[mi][0], af[mi][1], af[mi][2], af[mi][3], addr);
                }
            }
            // B fragments: one ldmatrix.x4 covers two n8 tiles
#pragma unroll
            for (int np = 0; np < 2; np++) {
                int n0w = wn * 32 + np * 16;
                uint32_t r0, r1, r2, r3;
                if (!TB) {
                    uint32_t addr = s2u(&Bs[buf][k0 + (lane & 7) + (((lane >> 3) & 1) << 3)]
                                            [n0w + ((lane >> 4) << 3)]);
                    LDSM_X4_T(r0, r1, r2, r3, addr);
                } else {
                    uint32_t addr = s2u(&Bs[buf][n0w + (lane & 7) + ((lane >> 4) << 3)]
                                            [k0 + (((lane >> 3) & 1) << 3)]);
                    LDSM_X4(r0, r1, r2, r3, addr);
                }
                bf[np * 2    ][0] = r0; bf[np * 2    ][1] = r1;
                bf[np * 2 + 1][0] = r2; bf[np * 2 + 1][1] = r3;
            }
#pragma unroll
            for (int mi = 0; mi < 4; mi++)
#pragma unroll
                for (int ni = 0; ni < 4; ni++) {
                    asm volatile(
                        "mma.sync.aligned.m16n8k16.row.col.f32.f16.f16.f32 "
                        "{%0,%1,%2,%3}, {%4,%5,%6,%7}, {%8,%9}, {%0,%1,%2,%3};\n"
                        : "+f"(acc[mi][ni][0]), "+f"(acc[mi][ni][1]),
                          "+f"(acc[mi][ni][2]), "+f"(acc[mi][ni][3])
                        : "r"(af[mi][0]), "r"(af[mi][1]), "r"(af[mi][2]), "r"(af[mi][3]),
                          "r"(bf[ni][0]), "r"(bf[ni][1]));
                }
        }
    };

    // Main loop: ld(t+1) -> compute(t) -> st(t+1 into other buffer) -> sync
    const int NT = K / BKH;
    ldA(0); ldB(0);
    stA(0); stB(0);
    __syncthreads();
    for (int t = 0; t < NT; t++) {
        if (t + 1 < NT) { ldA((t + 1) * BKH); ldB((t + 1) * BKH); }
        compute(t & 1);
        if (t + 1 < NT) { stA((t + 1) & 1); stB((t + 1) & 1); }
        __syncthreads();
    }

    // Epilogue
    float* Cp = Cb + sC * bz;
    const float* Rp = (EPI == 2) ? (resid + sR * bz) : nullptr;
#pragma unroll
    for (int mi = 0; mi < 4; mi++) {
        int r0 = m0 + wm * 64 + mi * 16 + (lane >> 2);
#pragma unroll
        for (int ni = 0; ni < 4; ni++) {
            int c0 = n0 + wn * 32 + ni * 8 + ((lane & 3) << 1);
            float v0 = acc[mi][ni][0], v1 = acc[mi][ni][1];
            float v2 = acc[mi][ni][2], v3 = acc[mi][ni][3];
            if (EPI == 1) { v0 *= alpha; v1 *= alpha; v2 *= alpha; v3 *= alpha; }
            if (EPI == 2) {
                float b0 = bias[r0], b1 = bias[r0 + 8];
                v0 += b0 + Rp[(size_t)r0 * ldc + c0];
                v1 += b0 + Rp[(size_t)r0 * ldc + c0 + 1];
                v2 += b1 + Rp[(size_t)(r0 + 8) * ldc + c0];
                v3 += b1 + Rp[(size_t)(r0 + 8) * ldc + c0 + 1];
            }
            *(float2*)(Cp + (size_t)r0       * ldc + c0) = make_float2(v0, v1);
            *(float2*)(Cp + (size_t)(r0 + 8) * ldc + c0) = make_float2(v2, v3);
        }
    }
}

// ---------------------------------------------------------------------------
// Row softmax over 4096 keys, in place. One block per (b, query) row.
// ---------------------------------------------------------------------------
__global__ __launch_bounds__(256) void softmax_kernel(float* __restrict__ S) {
    size_t row = blockIdx.x;
    float* r = S + row * (size_t)HW;
    int tid = threadIdx.x;
    float4 v[4];
    float mx = -3.4e38f;
#pragma unroll
    for (int i = 0; i < 4; i++) {
        v[i] = ((const float4*)r)[tid + i * 256];
        mx = fmaxf(mx, fmaxf(fmaxf(v[i].x, v[i].y), fmaxf(v[i].z, v[i].w)));
    }
#pragma unroll
    for (int o = 16; o > 0; o >>= 1) mx = fmaxf(mx, __shfl_xor_sync(0xffffffffu, mx, o));
    __shared__ float sred[8];
    if ((tid & 31) == 0) sred[tid >> 5] = mx;
    __syncthreads();
    float bm = sred[0];
#pragma unroll
    for (int i = 1; i < 8; i++) bm = fmaxf(bm, sred[i]);
    __syncthreads();
    const float L2E = 1.4426950408889634f;
    float sum = 0.f;
#pragma unroll
    for (int i = 0; i < 4; i++) {
        v[i].x = exp2f((v[i].x - bm) * L2E);
        v[i].y = exp2f((v[i].y - bm) * L2E);
        v[i].z = exp2f((v[i].z - bm) * L2E);
        v[i].w = exp2f((v[i].w - bm) * L2E);
        sum += v[i].x + v[i].y + v[i].z + v[i].w;
    }
#pragma unroll
    for (int o = 16; o > 0; o >>= 1) sum += __shfl_xor_sync(0xffffffffu, sum, o);
    if ((tid & 31) == 0) sred[tid >> 5] = sum;
    __syncthreads();
    float ts = 0.f;
#pragma unroll
    for (int i = 0; i < 8; i++) ts += sred[i];
    float inv = 1.f / ts;
#pragma unroll
    for (int i = 0; i < 4; i++) {
        v[i].x *= inv; v[i].y *= inv; v[i].z *= inv; v[i].w *= inv;
        ((float4*)r)[tid + i * 256] = v[i];
    }
}

// ---------------------------------------------------------------------------
// Launch
// ---------------------------------------------------------------------------
extern "C" void kernel_launch(void* const* d_in, const int* in_sizes, int n_in,
                              void* d_out, int out_size) {
    const float* x    = (const float*)d_in[0];
    const float* ln_w = (const float*)d_in[1];
    const float* ln_b = (const float*)d_in[2];
    const float* wq   = (const float*)d_in[3];
    const float* wk   = (const float*)d_in[4];
    const float* wv   = (const float*)d_in[5];
    const float* wp   = (const float*)d_in[6];
    const float* bp   = (const float*)d_in[7];
    float* out = (float*)d_out;

    void *big_p, *h_p, *q_p, *k_p, *v_p;
    cudaGetSymbolAddress(&big_p, g_big);
    cudaGetSymbolAddress(&h_p,   g_h);
    cudaGetSymbolAddress(&q_p,   g_q);
    cudaGetSymbolAddress(&k_p,   g_k);
    cudaGetSymbolAddress(&v_p,   g_v);
    float* col = (float*)big_p;    // steps 2-5
    float* s   = (float*)big_p;    // steps 6-8 (aliases col; disjoint lifetime)
    float* h   = (float*)h_p;      // steps 1-3
    float* o   = (float*)h_p;      // steps 8-9 (aliases h; disjoint lifetime)
    float* q   = (float*)q_p;
    float* k   = (float*)k_p;
    float* v   = (float*)v_p;

    const size_t sCHW = (size_t)C_DIM * HW;
    const size_t sCOL = (size_t)KCOL * HW;
    const size_t sS   = (size_t)HW * HW;
    const float attn_scale = 0.04419417382415922f;  // 512^-0.5

    // 1. LayerNorm
    ln_kernel<<<(BATCH * HW) / 256, 256>>>(x, ln_w, ln_b, h);

    // 2. im2col (shared by K and V convs)
    im2col_kernel<<<dim3(HW / 256, BATCH * KCOL), 256>>>(h, col);

    // 3. Q = Wq * h           [512 x 4096, K=512]
    gemm_f16<false, false, 0><<<dim3(HW / BN, C_DIM / BM, BATCH), 256>>>(
        wq, h, q, C_DIM, HW, C_DIM, C_DIM, HW, HW,
        0, sCHW, sCHW, 1.f, nullptr, nullptr, 0);

    // 4. K = Wk * col         [512 x 4096, K=4608]
    gemm_f16<false, false, 0><<<dim3(HW / BN, C_DIM / BM, BATCH), 256>>>(
        wk, col, k, C_DIM, HW, KCOL, KCOL, HW, HW,
        0, sCOL, sCHW, 1.f, nullptr, nullptr, 0);

    // 5. V = Wv * col
    gemm_f16<false, false, 0><<<dim3(HW / BN, C_DIM / BM, BATCH), 256>>>(
        wv, col, v, C_DIM, HW, KCOL, KCOL, HW, HW,
        0, sCOL, sCHW, 1.f, nullptr, nullptr, 0);

    // 6. S = (Q^T K) * scale  [4096 x 4096, K=512]  (A transposed layout)
    gemm_f16<true, false, 1><<<dim3(HW / BN, HW / BM, BATCH), 256>>>(
        q, k, s, HW, HW, C_DIM, HW, HW, HW,
        sCHW, sCHW, sS, attn_scale, nullptr, nullptr, 0);

    // 7. row softmax over keys, in place
    softmax_kernel<<<BATCH * HW, 256>>>(s);

    // 8. O = V * P^T          [512 x 4096, K=4096]  (B transposed layout)
    gemm_f16<false, true, 0><<<dim3(HW / BN, C_DIM / BM, BATCH), 256>>>(
        v, s, o, C_DIM, HW, HW, HW, HW, HW,
        sCHW, sS, sCHW, 1.f, nullptr, nullptr, 0);

    // 9. out = x + Wp * O + bp  (fused bias + residual epilogue)
    gemm_f16<false, false, 2><<<dim3(HW / BN, C_DIM / BM, BATCH), 256>>>(
        wp, o, out, C_DIM, HW, C_DIM, C_DIM, HW, HW,
        0, sCHW, sCHW, 1.f, bp, x, sCHW);
}